// round 14
// baseline (speedup 1.0000x reference)
#include <cuda_runtime.h>
#include <cuda_fp16.h>
#include <cstdint>
#include <math.h>

// Problem sizes (fixed): B=4, S=2048, D=N=K=2048
#define BSZ 4
#define SSZ 2048
#define DSZ 2048
#define NSZ 2048
#define KSZ 2048
#define MSZ (BSZ * SSZ)   // 8192

#define NCHUNK 64
#define CLEN (SSZ / NCHUNK)  // 32

// ---------------- GEMM tiling (fp16 mma m16n8k16 + ldmatrix) ----------------
#define BM 128
#define BN 128
#define BK 64                   // halves; 64*2B = 128B per row
#define NKITER (KSZ / BK)       // 32
#define NSTAGE 3
#define SSTR_H 72               // halves per smem row (36 words -> conflict-free)
#define A_BYTES (BM * SSTR_H * 2)            // 18432
#define B_BYTES (BN * SSTR_H * 2)            // 18432
#define STAGE_BYTES (A_BYTES + B_BYTES)      // 36864
#define SMEM_BYTES (NSTAGE * STAGE_BYTES)    // 110592 (108KB)

// ---------------- scratch (device globals; no allocation allowed) ----------
__device__ __half g_buf0[(size_t)MSZ * NSZ];   // dt_lin (fp16)
__device__ __half g_buf1[(size_t)MSZ * NSZ];   // Bp (fp16)
__device__ __half g_hh[(size_t)MSZ * NSZ];     // h_all (fp16 for GEMM3)
__device__ __half g_xh[(size_t)MSZ * KSZ];     // x in fp16
__device__ __half g_wh[3 * (size_t)NSZ * KSZ]; // W_dt | W_B | W_C in fp16
__device__ float  g_prod[BSZ * NCHUNK * NSZ];
__device__ float  g_hend[BSZ * NCHUNK * NSZ];
__device__ float  g_hin[BSZ * NCHUNK * NSZ];

// ---------------- helpers ----------------
__device__ __forceinline__ float ex2(float f) {
    float r; asm("ex2.approx.f32 %0, %1;" : "=f"(r) : "f"(f)); return r;
}
__device__ __forceinline__ float lg2(float f) {
    float r; asm("lg2.approx.f32 %0, %1;" : "=f"(r) : "f"(f)); return r;
}
__device__ __forceinline__ void cp16(uint32_t s, const void* g) {
    asm volatile("cp.async.cg.shared.global [%0], [%1], 16;" :: "r"(s), "l"(g));
}
__device__ __forceinline__ void ldmx4(uint32_t* r, uint32_t addr) {
    asm volatile(
        "ldmatrix.sync.aligned.m8n8.x4.shared.b16 {%0,%1,%2,%3}, [%4];"
        : "=r"(r[0]), "=r"(r[1]), "=r"(r[2]), "=r"(r[3]) : "r"(addr));
}

// mma.sync m16n8k16 fp16 -> fp32 acc: D += A*B (A rm 16x16, B cm 16x8)
__device__ __forceinline__ void mma16(float* d, const uint32_t* a, const uint32_t* b) {
    asm volatile(
        "mma.sync.aligned.m16n8k16.row.col.f32.f16.f16.f32 "
        "{%0,%1,%2,%3}, {%4,%5,%6,%7}, {%8,%9}, {%0,%1,%2,%3};"
        : "+f"(d[0]), "+f"(d[1]), "+f"(d[2]), "+f"(d[3])
        : "r"(a[0]), "r"(a[1]), "r"(a[2]), "r"(a[3]), "r"(b[0]), "r"(b[1]));
}

// fragment load into explicitly-named register buffers (compile-time buffer id)
#define LDFRAG(B, off) do {                                                   \
    _Pragma("unroll")                                                         \
    for (int mt = 0; mt < 4; mt++) ldmx4(af##B[mt], aAddr[mt] + (off));       \
    _Pragma("unroll")                                                         \
    for (int p = 0; p < 4; p++) {                                             \
        uint32_t r_[4];                                                       \
        ldmx4(r_, bAddr[p] + (off));                                          \
        bf##B[2*p][0] = r_[0];   bf##B[2*p][1] = r_[1];                       \
        bf##B[2*p+1][0] = r_[2]; bf##B[2*p+1][1] = r_[3];                     \
    }                                                                         \
} while (0)

// half of the mma block: mt in {MLO, MLO+1}
#define MMA_HALF(B, MLO) do {                                                 \
    _Pragma("unroll")                                                         \
    for (int mt = (MLO); mt < (MLO) + 2; mt++)                                \
        _Pragma("unroll")                                                     \
        for (int nt = 0; nt < 8; nt++)                                        \
            mma16(acc[mt][nt], af##B[mt], bf##B[nt]);                         \
} while (0)

#define MMA_ALL(B) do {                                                       \
    _Pragma("unroll")                                                         \
    for (int mt = 0; mt < 4; mt++)                                            \
        _Pragma("unroll")                                                     \
        for (int nt = 0; nt < 8; nt++)                                        \
            mma16(acc[mt][nt], af##B[mt], bf##B[nt]);                         \
} while (0)

// ---------------------------------------------------------------------------
// fp16 mma.sync GEMM (NT): C[m][n] = sum_k A[m][k] * W[n][k], fp32 accumulate
// CTA 128x128, 4 warps (2x2), warp tile 64x64, BK=64, 3-stage cp.async,
// register double-buffered ldmatrix pipeline with fine-grained MMA/load
// interleave (half-blocks).
// MODE 0: dual fp16 outputs (n0 < NSZ -> H0, else H1 at n0-NSZ).
// MODE 1: fp32 output F0 = acc + Dsk[n]*X[m][n] (X loads predicated off
//         when Dsk is zero).
// ---------------------------------------------------------------------------
template <int MODE>
__global__ __launch_bounds__(128, 2) void gemm_tc(
    const __half* __restrict__ A, const __half* __restrict__ W,
    __half* __restrict__ H0, __half* __restrict__ H1,
    float* __restrict__ F0,
    const float* __restrict__ X, const float* __restrict__ Dsk)
{
    extern __shared__ __half smem[];
    const int tid = threadIdx.x;
    const int wid = tid >> 5, lane = tid & 31;
    const int m0 = blockIdx.y * BM;
    const int n0 = blockIdx.x * BN;
    const int wm = (wid >> 1) * 64;      // 2 m-warps
    const int wn = (wid & 1) * 64;       // 2 n-warps
    const int lr = lane >> 2;            // 0..7 (epilogue row)
    const int lc = lane & 3;             // 0..3 (epilogue col)

    const uint32_t sbase = (uint32_t)__cvta_generic_to_shared(smem);

    // ldmatrix per-lane base addresses (bytes), within stage 0.
    uint32_t aAddr[4];
    #pragma unroll
    for (int mt = 0; mt < 4; mt++)
        aAddr[mt] = sbase +
            (uint32_t)(((wm + mt * 16 + (lane & 15)) * SSTR_H + ((lane >> 4) << 3)) * 2);
    uint32_t bAddr[4];
    #pragma unroll
    for (int ntp = 0; ntp < 4; ntp++)
        bAddr[ntp] = sbase + (uint32_t)A_BYTES +
            (uint32_t)(((wn + ntp * 16 + ((lane >> 4) << 3) + (lane & 7)) * SSTR_H
                        + (((lane >> 3) & 1) << 3)) * 2);

    float acc[4][8][4];
    #pragma unroll
    for (int i = 0; i < 4; i++)
        #pragma unroll
        for (int j = 0; j < 8; j++) {
            acc[i][j][0] = 0.f; acc[i][j][1] = 0.f;
            acc[i][j][2] = 0.f; acc[i][j][3] = 0.f;
        }

    // full-tile load (prologue only)
    auto load_tile = [&](int stage, int kt) {
        const __half* Ap = A + (size_t)m0 * KSZ + kt * BK;
        const __half* Wp = W + (size_t)n0 * KSZ + kt * BK;
        uint32_t baseA = sbase + (uint32_t)(stage * STAGE_BYTES);
        uint32_t baseB = baseA + (uint32_t)A_BYTES;
        #pragma unroll
        for (int i = 0; i < 8; i++) {
            int idx = tid + i * 128;
            int r = idx >> 3, c = idx & 7;
            cp16(baseA + (uint32_t)(r * (SSTR_H * 2) + c * 16),
                 Ap + (size_t)r * KSZ + c * 8);
        }
        #pragma unroll
        for (int i = 0; i < 8; i++) {
            int idx = tid + i * 128;
            int r = idx >> 3, c = idx & 7;
            cp16(baseB + (uint32_t)(r * (SSTR_H * 2) + c * 16),
                 Wp + (size_t)r * KSZ + c * 8);
        }
        asm volatile("cp.async.commit_group;");
    };

    // quarter-tile load: chunk group q (0..3), 4 cp.async per thread
    auto load_quarter = [&](int stage, int kt, int q) {
        const __half* Ap = A + (size_t)m0 * KSZ + kt * BK;
        const __half* Wp = W + (size_t)n0 * KSZ + kt * BK;
        uint32_t baseA = sbase + (uint32_t)(stage * STAGE_BYTES);
        uint32_t baseB = baseA + (uint32_t)A_BYTES;
        #pragma unroll
        for (int jj = 0; jj < 4; jj++) {
            int j = q * 4 + jj;
            int idx = tid + (j & 7) * 128;
            int r = idx >> 3, c = idx & 7;
            if (j < 8)
                cp16(baseA + (uint32_t)(r * (SSTR_H * 2) + c * 16),
                     Ap + (size_t)r * KSZ + c * 8);
            else
                cp16(baseB + (uint32_t)(r * (SSTR_H * 2) + c * 16),
                     Wp + (size_t)r * KSZ + c * 8);
        }
    };

    load_tile(0, 0);
    load_tile(1, 1);

    uint32_t af0[4][4], af1[4][4], bf0[8][2], bf1[8][2];

    #pragma unroll 1
    for (int kt = 0; kt < NKITER; kt++) {
        const int cur = kt % NSTAGE;
        if (kt < NKITER - 1) asm volatile("cp.async.wait_group 1;");
        else                 asm volatile("cp.async.wait_group 0;");
        __syncthreads();

        const uint32_t stOff = (uint32_t)(cur * STAGE_BYTES);
        const bool doLoad = (kt + 2 < NKITER);
        const int nstage = (kt + 2) % NSTAGE;

        // fine-grained interleave: LDSM / cp.async slots between mma half-blocks
        LDFRAG(0, stOff);
        if (doLoad) load_quarter(nstage, kt + 2, 0);
        LDFRAG(1, stOff + 32);
        MMA_HALF(0, 0);
        if (doLoad) load_quarter(nstage, kt + 2, 1);
        MMA_HALF(0, 2);
        LDFRAG(0, stOff + 64);
        MMA_HALF(1, 0);
        if (doLoad) load_quarter(nstage, kt + 2, 2);
        MMA_HALF(1, 2);
        LDFRAG(1, stOff + 96);
        MMA_HALF(0, 0);
        if (doLoad) {
            load_quarter(nstage, kt + 2, 3);
            asm volatile("cp.async.commit_group;");
        }
        MMA_HALF(0, 2);
        MMA_ALL(1);
    }

    if (MODE == 0) {
        // fp16 dual-output epilogue
        __half* Hw = H0;
        int ncol = n0;
        if (n0 >= NSZ) { Hw = H1; ncol = n0 - NSZ; }
        #pragma unroll
        for (int mt = 0; mt < 4; mt++) {
            #pragma unroll
            for (int nt = 0; nt < 8; nt++) {
                int r0 = m0 + wm + mt * 16 + lr;
                int c0 = ncol + wn + nt * 8 + lc * 2;
                __half2 v0 = __floats2half2_rn(acc[mt][nt][0], acc[mt][nt][1]);
                __half2 v1 = __floats2half2_rn(acc[mt][nt][2], acc[mt][nt][3]);
                *(__half2*)(Hw + (size_t)r0 * NSZ + c0) = v0;
                *(__half2*)(Hw + (size_t)(r0 + 8) * NSZ + c0) = v1;
            }
        }
    } else {
        // fp32 output with optional skip add
        #pragma unroll
        for (int mt = 0; mt < 4; mt++) {
            #pragma unroll
            for (int nt = 0; nt < 8; nt++) {
                int r0 = m0 + wm + mt * 16 + lr;
                int c0 = n0 + wn + nt * 8 + lc * 2;
                float2 v0 = { acc[mt][nt][0], acc[mt][nt][1] };
                float2 v1 = { acc[mt][nt][2], acc[mt][nt][3] };
                float2 d0 = *(const float2*)(Dsk + c0);
                if (d0.x != 0.0f || d0.y != 0.0f) {   // skip X traffic when D==0
                    float2 x0 = *(const float2*)(X + (size_t)r0 * NSZ + c0);
                    float2 x1 = *(const float2*)(X + (size_t)(r0 + 8) * NSZ + c0);
                    v0.x += d0.x * x0.x; v0.y += d0.y * x0.y;
                    v1.x += d0.x * x1.x; v1.y += d0.y * x1.y;
                }
                *(float2*)(F0 + (size_t)r0 * NSZ + c0) = v0;
                *(float2*)(F0 + (size_t)(r0 + 8) * NSZ + c0) = v1;
            }
        }
    }
}

// ---------------------------------------------------------------------------
// One-shot fp32 -> fp16 conversion with MLP=4: x -> g_xh, W_dt|W_B|W_C -> g_wh
// ---------------------------------------------------------------------------
#define XQ  ((size_t)MSZ * KSZ / 4)     // float4s in x       (4M)
#define WQ  ((size_t)NSZ * KSZ / 4)     // float4s per weight (1M)
#define XT  (XQ / 4)                    // threads for x
#define WT  (WQ / 4)                    // threads per weight
__global__ void tohalf_all(const float* __restrict__ x,
                           const float* __restrict__ w0,
                           const float* __restrict__ w1,
                           const float* __restrict__ w2,
                           __half* __restrict__ xh,
                           __half* __restrict__ wh)
{
    size_t i = (size_t)blockIdx.x * blockDim.x + threadIdx.x;
    const float* src;
    __half* dst;
    size_t base, seg;
    if (i < XT) {
        src = x; dst = xh; base = i; seg = XT;
    } else {
        size_t k = i - XT;
        int w = (int)(k / WT);
        src = (w == 0) ? w0 : (w == 1) ? w1 : w2;
        dst = wh + (size_t)w * NSZ * KSZ;
        base = k - (size_t)w * WT; seg = WT;
    }
    float4 v0 = ((const float4*)src)[base];
    float4 v1 = ((const float4*)src)[base + seg];
    float4 v2 = ((const float4*)src)[base + 2 * seg];
    float4 v3 = ((const float4*)src)[base + 3 * seg];
    __half2* d2 = (__half2*)dst;
    d2[2 * base]                 = __floats2half2_rn(v0.x, v0.y);
    d2[2 * base + 1]             = __floats2half2_rn(v0.z, v0.w);
    d2[2 * (base + seg)]         = __floats2half2_rn(v1.x, v1.y);
    d2[2 * (base + seg) + 1]     = __floats2half2_rn(v1.z, v1.w);
    d2[2 * (base + 2 * seg)]     = __floats2half2_rn(v2.x, v2.y);
    d2[2 * (base + 2 * seg) + 1] = __floats2half2_rn(v2.z, v2.w);
    d2[2 * (base + 3 * seg)]     = __floats2half2_rn(v3.x, v3.y);
    d2[2 * (base + 3 * seg) + 1] = __floats2half2_rn(v3.z, v3.w);
}

// ---------------------------------------------------------------------------
// Fused transform (scalar core)
// ---------------------------------------------------------------------------
__device__ __forceinline__ void transform(float dtl, float bp, float xv,
                                          float bd, float Aa,
                                          float& abar, float& inp)
{
    float z = dtl + bd;
    float e = ex2(z * 1.442695041f);
    float L = (z > 15.0f) ? z * 1.442695041f : lg2(1.0f + e);
    abar = ex2(L * Aa);
    float dt = L * 0.69314718056f;
    inp = dt * bp * xv;
}

// ---------------------------------------------------------------------------
// Chunked selective scan — half2 lanes (NCHUNK=64)
// ---------------------------------------------------------------------------
#define NH (NSZ / 2)   // 1024 half2 columns

__global__ void scan_pass1(const float* __restrict__ b_dt,
                           const float* __restrict__ A_log)
{
    int gid = blockIdx.x * blockDim.x + threadIdx.x;   // BSZ*NCHUNK*NH lanes
    int n2 = gid & (NH - 1);
    int c = (gid >> 10) & (NCHUNK - 1);
    int b = gid >> 16;
    int n = n2 * 2;
    float2 bd = *(const float2*)(b_dt + n);
    float2 al = *(const float2*)(A_log + n);
    float Aa0 = -expf(al.x), Aa1 = -expf(al.y);
    size_t base2 = (((size_t)(b * SSZ + c * CLEN)) * NSZ + n) / 2;
    float h0 = 0.f, h1 = 0.f, p0 = 1.f, p1 = 1.f;
    #pragma unroll 4
    for (int t = 0; t < CLEN; t++) {
        float2 d = __half22float2(((const __half2*)g_buf0)[base2]);
        float2 bp = __half22float2(((const __half2*)g_buf1)[base2]);
        float2 xv = __half22float2(((const __half2*)g_xh)[base2]);
        float ab0, in0, ab1, in1;
        transform(d.x, bp.x, xv.x, bd.x, Aa0, ab0, in0);
        transform(d.y, bp.y, xv.y, bd.y, Aa1, ab1, in1);
        h0 = ab0 * h0 + in0;  h1 = ab1 * h1 + in1;
        p0 *= ab0;            p1 *= ab1;
        base2 += NH;
    }
    size_t ci = ((size_t)(b * NCHUNK + c) * NSZ + n) / 2;
    ((float2*)g_prod)[ci] = make_float2(p0, p1);
    ((float2*)g_hend)[ci] = make_float2(h0, h1);
}

// pass2: batched register prefetch (MLP=64) before the dependent combine
#define P2B 32
__global__ void scan_pass2()
{
    int gid = blockIdx.x * blockDim.x + threadIdx.x;   // BSZ*NSZ lanes
    int n = gid & (NSZ - 1);
    int b = gid >> 11;
    float hin = 0.0f;
    #pragma unroll 1
    for (int c0 = 0; c0 < NCHUNK; c0 += P2B) {
        float p[P2B], h[P2B];
        #pragma unroll
        for (int j = 0; j < P2B; j++) {
            int ci = (b * NCHUNK + c0 + j) * NSZ + n;
            p[j] = g_prod[ci];
            h[j] = g_hend[ci];
        }
        #pragma unroll
        for (int j = 0; j < P2B; j++) {
            int ci = (b * NCHUNK + c0 + j) * NSZ + n;
            g_hin[ci] = hin;
            hin = p[j] * hin + h[j];
        }
    }
}

__global__ void scan_pass3(const float* __restrict__ b_dt,
                           const float* __restrict__ A_log)
{
    int gid = blockIdx.x * blockDim.x + threadIdx.x;
    int n2 = gid & (NH - 1);
    int c = (gid >> 10) & (NCHUNK - 1);
    int b = gid >> 16;
    int n = n2 * 2;
    float2 bd = *(const float2*)(b_dt + n);
    float2 al = *(const float2*)(A_log + n);
    float Aa0 = -expf(al.x), Aa1 = -expf(al.y);
    size_t base2 = (((size_t)(b * SSZ + c * CLEN)) * NSZ + n) / 2;
    size_t ci = ((size_t)(b * NCHUNK + c) * NSZ + n) / 2;
    float2 hin = ((const float2*)g_hin)[ci];
    float h0 = hin.x, h1 = hin.y;
    #pragma unroll 4
    for (int t = 0; t < CLEN; t++) {
        float2 d = __half22float2(((const __half2*)g_buf0)[base2]);
        float2 bp = __half22float2(((const __half2*)g_buf1)[base2]);
        float2 xv = __half22float2(((const __half2*)g_xh)[base2]);
        float ab0, in0, ab1, in1;
        transform(d.x, bp.x, xv.x, bd.x, Aa0, ab0, in0);
        transform(d.y, bp.y, xv.y, bd.y, Aa1, ab1, in1);
        h0 = ab0 * h0 + in0;  h1 = ab1 * h1 + in1;
        ((__half2*)g_hh)[base2] = __floats2half2_rn(h0, h1);
        base2 += NH;
    }
}

// ---------------------------------------------------------------------------
extern "C" void kernel_launch(void* const* d_in, const int* in_sizes, int n_in,
                              void* d_out, int out_size)
{
    const float* x      = (const float*)d_in[0];
    const float* W_dt   = (const float*)d_in[1];
    const float* b_dt   = (const float*)d_in[2];
    const float* W_B    = (const float*)d_in[3];
    const float* W_C    = (const float*)d_in[4];
    const float* A_log  = (const float*)d_in[5];
    const float* D_skip = (const float*)d_in[6];
    float* out = (float*)d_out;

    __half *buf0, *buf1, *xh, *wh, *hh;
    cudaGetSymbolAddress((void**)&buf0, g_buf0);
    cudaGetSymbolAddress((void**)&buf1, g_buf1);
    cudaGetSymbolAddress((void**)&xh, g_xh);
    cudaGetSymbolAddress((void**)&wh, g_wh);
    cudaGetSymbolAddress((void**)&hh, g_hh);
    __half* wc_h = wh + 2 * (size_t)NSZ * KSZ;

    cudaFuncSetAttribute(gemm_tc<0>, cudaFuncAttributeMaxDynamicSharedMemorySize, SMEM_BYTES);
    cudaFuncSetAttribute(gemm_tc<1>, cudaFuncAttributeMaxDynamicSharedMemorySize, SMEM_BYTES);

    // single fp16 conversion launch (x + 3 weights; weights contiguous in g_wh)
    size_t total_t = XT + 3 * WT;
    tohalf_all<<<(unsigned)(total_t / 256), 256>>>(x, W_dt, W_B, W_C, xh, wh);

    // dt_lin & Bp in ONE GEMM over stacked N=4096 (fp16 outputs)
    dim3 grid12(2 * NSZ / BN, MSZ / BM);   // (32, 64)
    gemm_tc<0><<<grid12, 128, SMEM_BYTES>>>(xh, wh, buf0, buf1, nullptr, nullptr, nullptr);

    // fused transform + chunked selective scan (half2 lanes, 64 chunks)
    scan_pass1<<<(BSZ * NCHUNK * NH) / 256, 256>>>(b_dt, A_log);
    scan_pass2<<<(BSZ * NSZ) / 256, 256>>>();
    scan_pass3<<<(BSZ * NCHUNK * NH) / 256, 256>>>(b_dt, A_log);

    // out = h @ W_C^T + D_skip * x   (skip fused in epilogue, predicated)
    dim3 grid3(NSZ / BN, MSZ / BM);        // (16, 64)
    gemm_tc<1><<<grid3, 128, SMEM_BYTES>>>(hh, wc_h, nullptr, nullptr, out, x, D_skip);
}

// round 15
// speedup vs baseline: 1.0273x; 1.0273x over previous
#include <cuda_runtime.h>
#include <cuda_fp16.h>
#include <cstdint>
#include <math.h>

// Problem sizes (fixed): B=4, S=2048, D=N=K=2048
#define BSZ 4
#define SSZ 2048
#define DSZ 2048
#define NSZ 2048
#define KSZ 2048
#define MSZ (BSZ * SSZ)   // 8192

#define NCHUNK 64
#define CLEN (SSZ / NCHUNK)  // 32

// ---------------- GEMM tiling (fp16 mma m16n8k16 + ldmatrix) ----------------
#define BM 128
#define BN 128
#define BK 64                   // halves; 64*2B = 128B per row
#define NKITER (KSZ / BK)       // 32
#define NSTAGE 3
#define SSTR_H 72               // halves per smem row (36 words -> conflict-free)
#define A_BYTES (BM * SSTR_H * 2)            // 18432
#define B_BYTES (BN * SSTR_H * 2)            // 18432
#define STAGE_BYTES (A_BYTES + B_BYTES)      // 36864
#define SMEM_BYTES (NSTAGE * STAGE_BYTES)    // 110592 (108KB)

// ---------------- scratch (device globals; no allocation allowed) ----------
__device__ __half g_buf0[(size_t)MSZ * NSZ];   // dt_lin (fp16)
__device__ __half g_buf1[(size_t)MSZ * NSZ];   // Bp (fp16)
__device__ __half g_hh[(size_t)MSZ * NSZ];     // h_all (fp16 for GEMM3)
__device__ __half g_xh[(size_t)MSZ * KSZ];     // x in fp16
__device__ __half g_wh[3 * (size_t)NSZ * KSZ]; // W_dt | W_B | W_C in fp16
__device__ float  g_prod[BSZ * NCHUNK * NSZ];
__device__ float  g_hend[BSZ * NCHUNK * NSZ];
__device__ float  g_hin[BSZ * NCHUNK * NSZ];

// ---------------- helpers ----------------
__device__ __forceinline__ float ex2(float f) {
    float r; asm("ex2.approx.f32 %0, %1;" : "=f"(r) : "f"(f)); return r;
}
__device__ __forceinline__ float lg2(float f) {
    float r; asm("lg2.approx.f32 %0, %1;" : "=f"(r) : "f"(f)); return r;
}
__device__ __forceinline__ void cp16(uint32_t s, const void* g) {
    asm volatile("cp.async.cg.shared.global [%0], [%1], 16;" :: "r"(s), "l"(g));
}
__device__ __forceinline__ void ldmx4(uint32_t* r, uint32_t addr) {
    asm volatile(
        "ldmatrix.sync.aligned.m8n8.x4.shared.b16 {%0,%1,%2,%3}, [%4];"
        : "=r"(r[0]), "=r"(r[1]), "=r"(r[2]), "=r"(r[3]) : "r"(addr));
}

// mma.sync m16n8k16 fp16 -> fp32 acc: D += A*B (A rm 16x16, B cm 16x8)
__device__ __forceinline__ void mma16(float* d, const uint32_t* a, const uint32_t* b) {
    asm volatile(
        "mma.sync.aligned.m16n8k16.row.col.f32.f16.f16.f32 "
        "{%0,%1,%2,%3}, {%4,%5,%6,%7}, {%8,%9}, {%0,%1,%2,%3};"
        : "+f"(d[0]), "+f"(d[1]), "+f"(d[2]), "+f"(d[3])
        : "r"(a[0]), "r"(a[1]), "r"(a[2]), "r"(a[3]), "r"(b[0]), "r"(b[1]));
}

// fragment load into explicitly-named register buffers (compile-time buffer id)
#define LDFRAG(B, off) do {                                                   \
    _Pragma("unroll")                                                         \
    for (int mt = 0; mt < 4; mt++) ldmx4(af##B[mt], aAddr[mt] + (off));       \
    _Pragma("unroll")                                                         \
    for (int p = 0; p < 4; p++) {                                             \
        uint32_t r_[4];                                                       \
        ldmx4(r_, bAddr[p] + (off));                                          \
        bf##B[2*p][0] = r_[0];   bf##B[2*p][1] = r_[1];                       \
        bf##B[2*p+1][0] = r_[2]; bf##B[2*p+1][1] = r_[3];                     \
    }                                                                         \
} while (0)

#define MMA_ALL(B) do {                                                       \
    _Pragma("unroll")                                                         \
    for (int mt = 0; mt < 4; mt++)                                            \
        _Pragma("unroll")                                                     \
        for (int nt = 0; nt < 8; nt++)                                        \
            mma16(acc[mt][nt], af##B[mt], bf##B[nt]);                         \
} while (0)

// ---------------------------------------------------------------------------
// fp16 mma.sync GEMM (NT): C[m][n] = sum_k A[m][k] * W[n][k], fp32 accumulate
// CTA 128x128, 4 warps (2x2), warp tile 64x64, BK=64, 3-stage cp.async,
// explicit register double-buffered ldmatrix pipeline (R13 schedule).
// MODE 0: dual fp16 outputs (n0 < NSZ -> H0, else H1 at n0-NSZ).
// MODE 1: fp32 output F0 = acc + Dsk[n]*X[m][n] (X loads predicated off
//         when Dsk is zero).
// ---------------------------------------------------------------------------
template <int MODE>
__global__ __launch_bounds__(128, 2) void gemm_tc(
    const __half* __restrict__ A, const __half* __restrict__ W,
    __half* __restrict__ H0, __half* __restrict__ H1,
    float* __restrict__ F0,
    const float* __restrict__ X, const float* __restrict__ Dsk)
{
    extern __shared__ __half smem[];
    const int tid = threadIdx.x;
    const int wid = tid >> 5, lane = tid & 31;
    const int m0 = blockIdx.y * BM;
    const int n0 = blockIdx.x * BN;
    const int wm = (wid >> 1) * 64;      // 2 m-warps
    const int wn = (wid & 1) * 64;       // 2 n-warps
    const int lr = lane >> 2;            // 0..7 (epilogue row)
    const int lc = lane & 3;             // 0..3 (epilogue col)

    const uint32_t sbase = (uint32_t)__cvta_generic_to_shared(smem);

    // ldmatrix per-lane base addresses (bytes), within stage 0.
    uint32_t aAddr[4];
    #pragma unroll
    for (int mt = 0; mt < 4; mt++)
        aAddr[mt] = sbase +
            (uint32_t)(((wm + mt * 16 + (lane & 15)) * SSTR_H + ((lane >> 4) << 3)) * 2);
    uint32_t bAddr[4];
    #pragma unroll
    for (int ntp = 0; ntp < 4; ntp++)
        bAddr[ntp] = sbase + (uint32_t)A_BYTES +
            (uint32_t)(((wn + ntp * 16 + ((lane >> 4) << 3) + (lane & 7)) * SSTR_H
                        + (((lane >> 3) & 1) << 3)) * 2);

    float acc[4][8][4];
    #pragma unroll
    for (int i = 0; i < 4; i++)
        #pragma unroll
        for (int j = 0; j < 8; j++) {
            acc[i][j][0] = 0.f; acc[i][j][1] = 0.f;
            acc[i][j][2] = 0.f; acc[i][j][3] = 0.f;
        }

    // full-tile load (prologue only)
    auto load_tile = [&](int stage, int kt) {
        const __half* Ap = A + (size_t)m0 * KSZ + kt * BK;
        const __half* Wp = W + (size_t)n0 * KSZ + kt * BK;
        uint32_t baseA = sbase + (uint32_t)(stage * STAGE_BYTES);
        uint32_t baseB = baseA + (uint32_t)A_BYTES;
        #pragma unroll
        for (int i = 0; i < 8; i++) {
            int idx = tid + i * 128;
            int r = idx >> 3, c = idx & 7;
            cp16(baseA + (uint32_t)(r * (SSTR_H * 2) + c * 16),
                 Ap + (size_t)r * KSZ + c * 8);
        }
        #pragma unroll
        for (int i = 0; i < 8; i++) {
            int idx = tid + i * 128;
            int r = idx >> 3, c = idx & 7;
            cp16(baseB + (uint32_t)(r * (SSTR_H * 2) + c * 16),
                 Wp + (size_t)r * KSZ + c * 8);
        }
        asm volatile("cp.async.commit_group;");
    };

    // quarter-tile load: chunk group q (0..3), 4 cp.async per thread
    auto load_quarter = [&](int stage, int kt, int q) {
        const __half* Ap = A + (size_t)m0 * KSZ + kt * BK;
        const __half* Wp = W + (size_t)n0 * KSZ + kt * BK;
        uint32_t baseA = sbase + (uint32_t)(stage * STAGE_BYTES);
        uint32_t baseB = baseA + (uint32_t)A_BYTES;
        #pragma unroll
        for (int jj = 0; jj < 4; jj++) {
            int j = q * 4 + jj;
            int idx = tid + (j & 7) * 128;
            int r = idx >> 3, c = idx & 7;
            if (j < 8)
                cp16(baseA + (uint32_t)(r * (SSTR_H * 2) + c * 16),
                     Ap + (size_t)r * KSZ + c * 8);
            else
                cp16(baseB + (uint32_t)(r * (SSTR_H * 2) + c * 16),
                     Wp + (size_t)r * KSZ + c * 8);
        }
    };

    load_tile(0, 0);
    load_tile(1, 1);

    uint32_t af0[4][4], af1[4][4], bf0[8][2], bf1[8][2];

    #pragma unroll 1
    for (int kt = 0; kt < NKITER; kt++) {
        const int cur = kt % NSTAGE;
        if (kt < NKITER - 1) asm volatile("cp.async.wait_group 1;");
        else                 asm volatile("cp.async.wait_group 0;");
        __syncthreads();

        const uint32_t stOff = (uint32_t)(cur * STAGE_BYTES);
        const bool doLoad = (kt + 2 < NKITER);
        const int nstage = (kt + 2) % NSTAGE;

        // R13 schedule: frag(kk+1) + cp.async quarter issued before mma(kk)
        LDFRAG(0, stOff);
        if (doLoad) load_quarter(nstage, kt + 2, 0);
        LDFRAG(1, stOff + 32);
        MMA_ALL(0);
        if (doLoad) load_quarter(nstage, kt + 2, 1);
        LDFRAG(0, stOff + 64);
        MMA_ALL(1);
        if (doLoad) load_quarter(nstage, kt + 2, 2);
        LDFRAG(1, stOff + 96);
        MMA_ALL(0);
        if (doLoad) {
            load_quarter(nstage, kt + 2, 3);
            asm volatile("cp.async.commit_group;");
        }
        MMA_ALL(1);
    }

    if (MODE == 0) {
        // fp16 dual-output epilogue
        __half* Hw = H0;
        int ncol = n0;
        if (n0 >= NSZ) { Hw = H1; ncol = n0 - NSZ; }
        #pragma unroll
        for (int mt = 0; mt < 4; mt++) {
            #pragma unroll
            for (int nt = 0; nt < 8; nt++) {
                int r0 = m0 + wm + mt * 16 + lr;
                int c0 = ncol + wn + nt * 8 + lc * 2;
                __half2 v0 = __floats2half2_rn(acc[mt][nt][0], acc[mt][nt][1]);
                __half2 v1 = __floats2half2_rn(acc[mt][nt][2], acc[mt][nt][3]);
                *(__half2*)(Hw + (size_t)r0 * NSZ + c0) = v0;
                *(__half2*)(Hw + (size_t)(r0 + 8) * NSZ + c0) = v1;
            }
        }
    } else {
        // fp32 output with optional skip add
        #pragma unroll
        for (int mt = 0; mt < 4; mt++) {
            #pragma unroll
            for (int nt = 0; nt < 8; nt++) {
                int r0 = m0 + wm + mt * 16 + lr;
                int c0 = n0 + wn + nt * 8 + lc * 2;
                float2 v0 = { acc[mt][nt][0], acc[mt][nt][1] };
                float2 v1 = { acc[mt][nt][2], acc[mt][nt][3] };
                float2 d0 = *(const float2*)(Dsk + c0);
                if (d0.x != 0.0f || d0.y != 0.0f) {   // skip X traffic when D==0
                    float2 x0 = *(const float2*)(X + (size_t)r0 * NSZ + c0);
                    float2 x1 = *(const float2*)(X + (size_t)(r0 + 8) * NSZ + c0);
                    v0.x += d0.x * x0.x; v0.y += d0.y * x0.y;
                    v1.x += d0.x * x1.x; v1.y += d0.y * x1.y;
                }
                *(float2*)(F0 + (size_t)r0 * NSZ + c0) = v0;
                *(float2*)(F0 + (size_t)(r0 + 8) * NSZ + c0) = v1;
            }
        }
    }
}

// ---------------------------------------------------------------------------
// One-shot fp32 -> fp16 conversion with MLP=4: x -> g_xh, W_dt|W_B|W_C -> g_wh
// ---------------------------------------------------------------------------
#define XQ  ((size_t)MSZ * KSZ / 4)     // float4s in x       (4M)
#define WQ  ((size_t)NSZ * KSZ / 4)     // float4s per weight (1M)
#define XT  (XQ / 4)                    // threads for x
#define WT  (WQ / 4)                    // threads per weight
__global__ void tohalf_all(const float* __restrict__ x,
                           const float* __restrict__ w0,
                           const float* __restrict__ w1,
                           const float* __restrict__ w2,
                           __half* __restrict__ xh,
                           __half* __restrict__ wh)
{
    size_t i = (size_t)blockIdx.x * blockDim.x + threadIdx.x;
    const float* src;
    __half* dst;
    size_t base, seg;
    if (i < XT) {
        src = x; dst = xh; base = i; seg = XT;
    } else {
        size_t k = i - XT;
        int w = (int)(k / WT);
        src = (w == 0) ? w0 : (w == 1) ? w1 : w2;
        dst = wh + (size_t)w * NSZ * KSZ;
        base = k - (size_t)w * WT; seg = WT;
    }
    float4 v0 = ((const float4*)src)[base];
    float4 v1 = ((const float4*)src)[base + seg];
    float4 v2 = ((const float4*)src)[base + 2 * seg];
    float4 v3 = ((const float4*)src)[base + 3 * seg];
    __half2* d2 = (__half2*)dst;
    d2[2 * base]                 = __floats2half2_rn(v0.x, v0.y);
    d2[2 * base + 1]             = __floats2half2_rn(v0.z, v0.w);
    d2[2 * (base + seg)]         = __floats2half2_rn(v1.x, v1.y);
    d2[2 * (base + seg) + 1]     = __floats2half2_rn(v1.z, v1.w);
    d2[2 * (base + 2 * seg)]     = __floats2half2_rn(v2.x, v2.y);
    d2[2 * (base + 2 * seg) + 1] = __floats2half2_rn(v2.z, v2.w);
    d2[2 * (base + 3 * seg)]     = __floats2half2_rn(v3.x, v3.y);
    d2[2 * (base + 3 * seg) + 1] = __floats2half2_rn(v3.z, v3.w);
}

// ---------------------------------------------------------------------------
// Fused transform (scalar core)
// ---------------------------------------------------------------------------
__device__ __forceinline__ void transform(float dtl, float bp, float xv,
                                          float bd, float Aa,
                                          float& abar, float& inp)
{
    float z = dtl + bd;
    float e = ex2(z * 1.442695041f);
    float L = (z > 15.0f) ? z * 1.442695041f : lg2(1.0f + e);
    abar = ex2(L * Aa);
    float dt = L * 0.69314718056f;
    inp = dt * bp * xv;
}

// ---------------------------------------------------------------------------
// Chunked selective scan — half2 lanes (NCHUNK=64)
// ---------------------------------------------------------------------------
#define NH (NSZ / 2)   // 1024 half2 columns

__global__ void scan_pass1(const float* __restrict__ b_dt,
                           const float* __restrict__ A_log)
{
    int gid = blockIdx.x * blockDim.x + threadIdx.x;   // BSZ*NCHUNK*NH lanes
    int n2 = gid & (NH - 1);
    int c = (gid >> 10) & (NCHUNK - 1);
    int b = gid >> 16;
    int n = n2 * 2;
    float2 bd = *(const float2*)(b_dt + n);
    float2 al = *(const float2*)(A_log + n);
    float Aa0 = -expf(al.x), Aa1 = -expf(al.y);
    size_t base2 = (((size_t)(b * SSZ + c * CLEN)) * NSZ + n) / 2;
    float h0 = 0.f, h1 = 0.f, p0 = 1.f, p1 = 1.f;
    #pragma unroll 4
    for (int t = 0; t < CLEN; t++) {
        float2 d = __half22float2(((const __half2*)g_buf0)[base2]);
        float2 bp = __half22float2(((const __half2*)g_buf1)[base2]);
        float2 xv = __half22float2(((const __half2*)g_xh)[base2]);
        float ab0, in0, ab1, in1;
        transform(d.x, bp.x, xv.x, bd.x, Aa0, ab0, in0);
        transform(d.y, bp.y, xv.y, bd.y, Aa1, ab1, in1);
        h0 = ab0 * h0 + in0;  h1 = ab1 * h1 + in1;
        p0 *= ab0;            p1 *= ab1;
        base2 += NH;
    }
    size_t ci = ((size_t)(b * NCHUNK + c) * NSZ + n) / 2;
    ((float2*)g_prod)[ci] = make_float2(p0, p1);
    ((float2*)g_hend)[ci] = make_float2(h0, h1);
}

// pass2: batched register prefetch (MLP=64) before the dependent combine
#define P2B 32
__global__ void scan_pass2()
{
    int gid = blockIdx.x * blockDim.x + threadIdx.x;   // BSZ*NSZ lanes
    int n = gid & (NSZ - 1);
    int b = gid >> 11;
    float hin = 0.0f;
    #pragma unroll 1
    for (int c0 = 0; c0 < NCHUNK; c0 += P2B) {
        float p[P2B], h[P2B];
        #pragma unroll
        for (int j = 0; j < P2B; j++) {
            int ci = (b * NCHUNK + c0 + j) * NSZ + n;
            p[j] = g_prod[ci];
            h[j] = g_hend[ci];
        }
        #pragma unroll
        for (int j = 0; j < P2B; j++) {
            int ci = (b * NCHUNK + c0 + j) * NSZ + n;
            g_hin[ci] = hin;
            hin = p[j] * hin + h[j];
        }
    }
}

__global__ void scan_pass3(const float* __restrict__ b_dt,
                           const float* __restrict__ A_log)
{
    int gid = blockIdx.x * blockDim.x + threadIdx.x;
    int n2 = gid & (NH - 1);
    int c = (gid >> 10) & (NCHUNK - 1);
    int b = gid >> 16;
    int n = n2 * 2;
    float2 bd = *(const float2*)(b_dt + n);
    float2 al = *(const float2*)(A_log + n);
    float Aa0 = -expf(al.x), Aa1 = -expf(al.y);
    size_t base2 = (((size_t)(b * SSZ + c * CLEN)) * NSZ + n) / 2;
    size_t ci = ((size_t)(b * NCHUNK + c) * NSZ + n) / 2;
    float2 hin = ((const float2*)g_hin)[ci];
    float h0 = hin.x, h1 = hin.y;
    #pragma unroll 4
    for (int t = 0; t < CLEN; t++) {
        float2 d = __half22float2(((const __half2*)g_buf0)[base2]);
        float2 bp = __half22float2(((const __half2*)g_buf1)[base2]);
        float2 xv = __half22float2(((const __half2*)g_xh)[base2]);
        float ab0, in0, ab1, in1;
        transform(d.x, bp.x, xv.x, bd.x, Aa0, ab0, in0);
        transform(d.y, bp.y, xv.y, bd.y, Aa1, ab1, in1);
        h0 = ab0 * h0 + in0;  h1 = ab1 * h1 + in1;
        ((__half2*)g_hh)[base2] = __floats2half2_rn(h0, h1);
        base2 += NH;
    }
}

// ---------------------------------------------------------------------------
extern "C" void kernel_launch(void* const* d_in, const int* in_sizes, int n_in,
                              void* d_out, int out_size)
{
    const float* x      = (const float*)d_in[0];
    const float* W_dt   = (const float*)d_in[1];
    const float* b_dt   = (const float*)d_in[2];
    const float* W_B    = (const float*)d_in[3];
    const float* W_C    = (const float*)d_in[4];
    const float* A_log  = (const float*)d_in[5];
    const float* D_skip = (const float*)d_in[6];
    float* out = (float*)d_out;

    __half *buf0, *buf1, *xh, *wh, *hh;
    cudaGetSymbolAddress((void**)&buf0, g_buf0);
    cudaGetSymbolAddress((void**)&buf1, g_buf1);
    cudaGetSymbolAddress((void**)&xh, g_xh);
    cudaGetSymbolAddress((void**)&wh, g_wh);
    cudaGetSymbolAddress((void**)&hh, g_hh);
    __half* wc_h = wh + 2 * (size_t)NSZ * KSZ;

    cudaFuncSetAttribute(gemm_tc<0>, cudaFuncAttributeMaxDynamicSharedMemorySize, SMEM_BYTES);
    cudaFuncSetAttribute(gemm_tc<1>, cudaFuncAttributeMaxDynamicSharedMemorySize, SMEM_BYTES);

    // single fp16 conversion launch (x + 3 weights; weights contiguous in g_wh)
    size_t total_t = XT + 3 * WT;
    tohalf_all<<<(unsigned)(total_t / 256), 256>>>(x, W_dt, W_B, W_C, xh, wh);

    // dt_lin & Bp in ONE GEMM over stacked N=4096 (fp16 outputs)
    dim3 grid12(2 * NSZ / BN, MSZ / BM);   // (32, 64)
    gemm_tc<0><<<grid12, 128, SMEM_BYTES>>>(xh, wh, buf0, buf1, nullptr, nullptr, nullptr);

    // fused transform + chunked selective scan (half2 lanes, 64 chunks)
    scan_pass1<<<(BSZ * NCHUNK * NH) / 256, 256>>>(b_dt, A_log);
    scan_pass2<<<(BSZ * NSZ) / 256, 256>>>();
    scan_pass3<<<(BSZ * NCHUNK * NH) / 256, 256>>>(b_dt, A_log);

    // out = h @ W_C^T + D_skip * x   (skip fused in epilogue, predicated)
    dim3 grid3(NSZ / BN, MSZ / BM);        // (16, 64)
    gemm_tc<1><<<grid3, 128, SMEM_BYTES>>>(hh, wc_h, nullptr, nullptr, out, x, D_skip);
}